// round 8
// baseline (speedup 1.0000x reference)
#include <cuda_runtime.h>
#include <cuda_fp16.h>
#include <cstdint>

// ---------------- problem constants ----------------
#define TOK_LABEL   2
#define ACT_START   5
#define TIME_START  69
#define NB          8
#define NT_SEQ      2048
#define ND          1024
#define N_ACT       64
#define N_TIME      32
#define N_COLS      96
#define M_TOT       (NB * NT_SEQ)
#define ACT_ELEMS   ((size_t)M_TOT * N_ACT)

// GEMM tiling
#define BM       64
#define BK       64
#define NTILES   (ND / BK)     // 16
#define ASTR     72            // smem row stride in halves
#define BSTR     72

// ---------------- scratch ----------------
__device__ __align__(16) __half g_Bh[N_COLS * ND];   // folded weights, fp16
__device__ int   g_qlist[NB][NT_SEQ];
__device__ int   g_klist[NB][NT_SEQ];
__device__ int   g_kcls [NB][NT_SEQ];
__device__ int   g_qcnt[NB];
__device__ int   g_kcnt[NB];

// ---------------- helpers ----------------
__device__ __forceinline__ float softplus_f(float x) {
    return (x > 20.0f) ? x : log1pf(expf(x));
}
__device__ __forceinline__ uint32_t smem_u32(const void* p) {
    uint32_t a;
    asm("{ .reg .u64 t; cvta.to.shared.u64 t, %1; cvt.u32.u64 %0, t; }" : "=r"(a) : "l"(p));
    return a;
}
__device__ __forceinline__ void ldsm4(uint32_t* r, uint32_t addr) {
    asm volatile("ldmatrix.sync.aligned.m8n8.x4.shared.b16 {%0,%1,%2,%3}, [%4];"
                 : "=r"(r[0]), "=r"(r[1]), "=r"(r[2]), "=r"(r[3]) : "r"(addr));
}
__device__ __forceinline__ void mma_f16(float* c, const uint32_t* a, const uint32_t* b) {
    asm volatile(
        "mma.sync.aligned.m16n8k16.row.col.f32.f16.f16.f32 "
        "{%0,%1,%2,%3}, {%4,%5,%6,%7}, {%8,%9}, {%0,%1,%2,%3};"
        : "+f"(c[0]), "+f"(c[1]), "+f"(c[2]), "+f"(c[3])
        : "r"(a[0]), "r"(a[1]), "r"(a[2]), "r"(a[3]), "r"(b[0]), "r"(b[1]));
}
// convert 16 fp32 -> 16 fp16 packed into 2 uint4
__device__ __forceinline__ void cvt16(const float4* f, uint4& o0, uint4& o1) {
    uint32_t u[8];
    #pragma unroll
    for (int i = 0; i < 4; i++) {
        __half2 a = __float22half2_rn(make_float2(f[i].x, f[i].y));
        __half2 b = __float22half2_rn(make_float2(f[i].z, f[i].w));
        u[2 * i]     = *(uint32_t*)&a;
        u[2 * i + 1] = *(uint32_t*)&b;
    }
    o0 = make_uint4(u[0], u[1], u[2], u[3]);
    o1 = make_uint4(u[4], u[5], u[6], u[7]);
}

// ---------------- kernel 1: weight-fold (-> fp16) + PARALLEL token scan ----------------
#define WC_BLOCKS 384   // 96*1024 / 256

__global__ void prep_kernel(const float* __restrict__ E,
                            const float* __restrict__ Wn,
                            const float* __restrict__ Wt,
                            const float* __restrict__ tsa, const float* __restrict__ tst,
                            const int* __restrict__ tokens) {
    if (blockIdx.x < WC_BLOCKS) {
        int i = blockIdx.x * blockDim.x + threadIdx.x;
        float sa = softplus_f(*tsa);
        float st = softplus_f(*tst);
        int r = i >> 10;
        int c = i & (ND - 1);
        float v;
        if (r < N_ACT)
            v = Wn[r * ND + c] + sa * E[(ACT_START + r) * ND + c];
        else
            v = Wt[(r - N_ACT) * ND + c] + st * E[(TIME_START + (r - N_ACT)) * ND + c];
        g_Bh[i] = __float2half_rn(v);
        return;
    }
    // parallel scan: one block per batch; list order is irrelevant (consumed as a set)
    const int b   = blockIdx.x - WC_BLOCKS;
    const int tid = threadIdx.x;
    const int* tk = tokens + b * NT_SEQ;

    if (tid == 0) { g_qcnt[b] = 0; g_kcnt[b] = 0; }   // block-local zeroing, race-free
    __syncthreads();

    #pragma unroll
    for (int r = 0; r < NT_SEQ / 256; r++) {
        int pos = tid + r * 256;
        int tok = tk[pos];
        if (tok == TOK_LABEL) {
            int s = atomicAdd(&g_qcnt[b], 1);
            g_qlist[b][s] = pos;
        }
        if (pos >= 1 && tok >= ACT_START && tk[pos - 1] == TOK_LABEL) {
            int s = atomicAdd(&g_kcnt[b], 1);
            g_klist[b][s] = pos;
            g_kcls[b][s]  = (tok < TIME_START) ? (tok - ACT_START)
                                               : (N_ACT + (tok - TIME_START));
        }
    }
}

// ---------------- kernel 2: fp16 GEMM via mma.sync (m32xn24 warp tiles) ----------------
__global__ __launch_bounds__(256, 2)
void gemm_kernel(const float* __restrict__ h, float* __restrict__ out,
                 const float* __restrict__ bn, const float* __restrict__ bt) {
    __shared__ __align__(16) __half sA[2][BM * ASTR];       // 2 x 9216 B
    __shared__ __align__(16) __half sB[2][N_COLS * BSTR];   // 2 x 13824 B
    __shared__ float s_bias[N_COLS];

    const int tid  = threadIdx.x;
    const int warp = tid >> 5;
    const int lane = tid & 31;
    const int wm   = warp & 1;       // m-tile of 32
    const int wn   = warp >> 1;      // n-tile of 24
    const int m0   = blockIdx.x * BM;

    if (tid < N_COLS) s_bias[tid] = (tid < N_ACT) ? bn[tid] : bt[tid - N_ACT];

    // A: 64 rows x 64 k fp32 per tile; 4 threads/row x 16 floats
    const int aRow = tid >> 2;
    const int aK   = (tid & 3) * 16;
    const float* gA = h + (size_t)(m0 + aRow) * ND + aK;

    // B: 96 rows x 64 halves per tile; threads 0..191, 2/row x 32 halves
    const int bN = tid >> 1;
    const int bK = (tid & 1) * 32;
    const __half* gB = g_Bh + (size_t)bN * ND + bK;

    float acc[2][3][4];
    #pragma unroll
    for (int i = 0; i < 2; i++)
        #pragma unroll
        for (int j = 0; j < 3; j++)
            #pragma unroll
            for (int c = 0; c < 4; c++) acc[i][j][c] = 0.0f;

    float4 fa[4];
    uint4  pb[4];

    // ---- prologue: tile 0 load + store to stage 0 ----
    #pragma unroll
    for (int i = 0; i < 4; i++) fa[i] = *(const float4*)(gA + 4 * i);
    if (tid < 192)
        #pragma unroll
        for (int i = 0; i < 4; i++) pb[i] = *(const uint4*)(gB + 8 * i);
    {
        uint4 o0, o1; cvt16(fa, o0, o1);
        __half* dA = &sA[0][aRow * ASTR + aK];
        *(uint4*)dA = o0; *(uint4*)(dA + 8) = o1;
        if (tid < 192) {
            __half* dB = &sB[0][bN * BSTR + bK];
            #pragma unroll
            for (int i = 0; i < 4; i++) *(uint4*)(dB + 8 * i) = pb[i];
        }
    }
    __syncthreads();

    const uint32_t uA0 = smem_u32(&sA[0][0]);
    const uint32_t uA1 = smem_u32(&sA[1][0]);
    const uint32_t aoff0 = (uint32_t)(((wm * 32 +      (lane & 15)) * ASTR + (lane >> 4) * 8) * 2);
    const uint32_t aoff1 = (uint32_t)(((wm * 32 + 16 + (lane & 15)) * ASTR + (lane >> 4) * 8) * 2);

    for (int t = 0; t < NTILES; t++) {
        const int cur = t & 1;
        // ---- prefetch tile t+1 into regs ----
        if (t + 1 < NTILES) {
            const float* a2 = gA + (t + 1) * BK;
            #pragma unroll
            for (int i = 0; i < 4; i++) fa[i] = *(const float4*)(a2 + 4 * i);
            if (tid < 192) {
                const __half* b2 = gB + (t + 1) * BK;
                #pragma unroll
                for (int i = 0; i < 4; i++) pb[i] = *(const uint4*)(b2 + 8 * i);
            }
        }

        // ---- compute current tile: 4 k16 steps ----
        const uint32_t uA = cur ? uA1 : uA0;
        const __half* sb = &sB[cur][0];
        #pragma unroll
        for (int ks = 0; ks < 4; ks++) {
            uint32_t a0[4], a1[4];
            ldsm4(a0, uA + aoff0 + ks * 32);
            ldsm4(a1, uA + aoff1 + ks * 32);
            uint32_t b[3][2];
            #pragma unroll
            for (int j = 0; j < 3; j++) {
                int n = wn * 24 + j * 8 + (lane >> 2);
                const __half* p = sb + n * BSTR + ks * 16 + (lane & 3) * 2;
                b[j][0] = *(const uint32_t*)p;
                b[j][1] = *(const uint32_t*)(p + 8);
            }
            #pragma unroll
            for (int j = 0; j < 3; j++) {
                mma_f16(acc[0][j], a0, b[j]);
                mma_f16(acc[1][j], a1, b[j]);
            }
        }

        // ---- store prefetched tile into other stage ----
        if (t + 1 < NTILES) {
            const int nxt = cur ^ 1;
            uint4 o0, o1; cvt16(fa, o0, o1);
            __half* dA = &sA[nxt][aRow * ASTR + aK];
            *(uint4*)dA = o0; *(uint4*)(dA + 8) = o1;
            if (tid < 192) {
                __half* dB = &sB[nxt][bN * BSTR + bK];
                #pragma unroll
                for (int i = 0; i < 4; i++) *(uint4*)(dB + 8 * i) = pb[i];
            }
        }
        __syncthreads();
    }

    // ---- epilogue ----
    float* out_time = out + ACT_ELEMS;
    #pragma unroll
    for (int mt = 0; mt < 2; mt++) {
        size_t r0 = (size_t)m0 + wm * 32 + mt * 16 + (lane >> 2);
        size_t r1 = r0 + 8;
        #pragma unroll
        for (int j = 0; j < 3; j++) {
            int c0 = wn * 24 + j * 8 + (lane & 3) * 2;
            float b0 = s_bias[c0], b1 = s_bias[c0 + 1];
            float2 v0 = make_float2(acc[mt][j][0] + b0, acc[mt][j][1] + b1);
            float2 v1 = make_float2(acc[mt][j][2] + b0, acc[mt][j][3] + b1);
            if (c0 < N_ACT) {
                *(float2*)(out + r0 * N_ACT + c0) = v0;
                *(float2*)(out + r1 * N_ACT + c0) = v1;
            } else {
                int ct = c0 - N_ACT;
                *(float2*)(out_time + r0 * N_TIME + ct) = v0;
                *(float2*)(out_time + r1 * N_TIME + ct) = v1;
            }
        }
    }
}

// ---------------- kernel 3: retrieval/copy head (per-warp norms) ----------------
__global__ __launch_bounds__(256)
void copy_kernel(const float* __restrict__ h, float* __restrict__ out,
                 const float* __restrict__ csa, const float* __restrict__ cst,
                 const float* __restrict__ cta, const float* __restrict__ ctt) {
    const int b    = blockIdx.y;
    const int tid  = threadIdx.x;
    const int warp = tid >> 5;
    const int lane = tid & 31;
    const int qcnt = g_qcnt[b];
    const int kc   = g_kcnt[b];

    __shared__ float s_acc[N_COLS];

    const float tau_a = softplus_f(*cta);
    const float tau_t = softplus_f(*ctt);
    const float sca   = softplus_f(*csa);
    const float sct   = softplus_f(*cst);
    const float* hb   = h + (size_t)b * NT_SEQ * ND;

    for (int qi = blockIdx.x; qi < qcnt; qi += gridDim.x) {
        __syncthreads();                 // prev iteration's reads of s_acc done
        if (tid < N_COLS) s_acc[tid] = 0.0f;
        const int q = g_qlist[b][qi];
        const float* hq = hb + (size_t)q * ND;
        float4 qv[8];
        float nq = 0.0f;
        #pragma unroll
        for (int c = 0; c < 8; c++) {
            qv[c] = *(const float4*)(hq + c * 128 + lane * 4);
            nq += qv[c].x*qv[c].x + qv[c].y*qv[c].y + qv[c].z*qv[c].z + qv[c].w*qv[c].w;
        }
        #pragma unroll
        for (int o = 16; o; o >>= 1) nq += __shfl_xor_sync(0xffffffffu, nq, o);
        // each warp's 32 lanes cover the full 1024-dim row, so nq == ||q||^2 already
        const float rnq = 1.0f / fmaxf(sqrtf(nq), 1e-12f);
        __syncthreads();                 // s_acc zeroing visible before atomics

        // 2 keys per warp per round for memory-level parallelism
        for (int j = warp; j < kc; j += 16) {
            const int jb = j + 8;
            const bool h2 = jb < kc;
            int k1 = g_klist[b][j];
            int k2 = h2 ? g_klist[b][jb] : k1;
            bool m1 = (k1 < q);
            bool m2 = h2 && (k2 < q);
            if (!m1 && !m2) continue;
            const float* p1 = hb + (size_t)k1 * ND;
            const float* p2 = hb + (size_t)k2 * ND;
            float d1 = 0.0f, n1 = 0.0f, d2 = 0.0f, n2 = 0.0f;
            #pragma unroll
            for (int c = 0; c < 8; c++) {
                float4 a = *(const float4*)(p1 + c * 128 + lane * 4);
                float4 v = *(const float4*)(p2 + c * 128 + lane * 4);
                d1 += qv[c].x*a.x + qv[c].y*a.y + qv[c].z*a.z + qv[c].w*a.w;
                n1 += a.x*a.x + a.y*a.y + a.z*a.z + a.w*a.w;
                d2 += qv[c].x*v.x + qv[c].y*v.y + qv[c].z*v.z + qv[c].w*v.w;
                n2 += v.x*v.x + v.y*v.y + v.z*v.z + v.w*v.w;
            }
            #pragma unroll
            for (int o = 16; o; o >>= 1) {
                d1 += __shfl_xor_sync(0xffffffffu, d1, o);
                n1 += __shfl_xor_sync(0xffffffffu, n1, o);
                d2 += __shfl_xor_sync(0xffffffffu, d2, o);
                n2 += __shfl_xor_sync(0xffffffffu, n2, o);
            }
            if (lane == 0) {
                if (m1) {
                    int cls = g_kcls[b][j];
                    float sim = d1 * rnq / fmaxf(sqrtf(n1), 1e-12f);
                    atomicAdd(&s_acc[cls], sim * (cls < N_ACT ? tau_a : tau_t));
                }
                if (m2) {
                    int cls = g_kcls[b][jb];
                    float sim = d2 * rnq / fmaxf(sqrtf(n2), 1e-12f);
                    atomicAdd(&s_acc[cls], sim * (cls < N_ACT ? tau_a : tau_t));
                }
            }
        }
        __syncthreads();

        size_t m = (size_t)b * NT_SEQ + q;
        if (tid < N_ACT) {
            out[m * N_ACT + tid] += sca * s_acc[tid];
        } else if (tid < N_COLS) {
            float* out_time = out + ACT_ELEMS;
            out_time[m * N_TIME + (tid - N_ACT)] += sct * s_acc[tid];
        }
    }
}

// ---------------- launch ----------------
extern "C" void kernel_launch(void* const* d_in, const int* in_sizes, int n_in,
                              void* d_out, int out_size) {
    const int*   tokens = (const int*)  d_in[0];
    const float* h      = (const float*)d_in[1];
    const float* E      = (const float*)d_in[2];
    const float* Wn     = (const float*)d_in[3];
    const float* bn     = (const float*)d_in[4];
    const float* Wt     = (const float*)d_in[5];
    const float* bt     = (const float*)d_in[6];
    const float* tsa    = (const float*)d_in[7];
    const float* tst    = (const float*)d_in[8];
    const float* csa    = (const float*)d_in[9];
    const float* cst    = (const float*)d_in[10];
    const float* cta    = (const float*)d_in[11];
    const float* ctt    = (const float*)d_in[12];
    float* out = (float*)d_out;

    prep_kernel<<<WC_BLOCKS + NB, 256>>>(E, Wn, Wt, tsa, tst, tokens);
    gemm_kernel<<<M_TOT / BM, 256>>>(h, out, bn, bt);
    copy_kernel<<<dim3(48, NB), 256>>>(h, out, csa, cst, cta, ctt);
}

// round 9
// speedup vs baseline: 1.0675x; 1.0675x over previous
#include <cuda_runtime.h>
#include <cuda_fp16.h>
#include <cstdint>

// ---------------- problem constants ----------------
#define TOK_LABEL   2
#define ACT_START   5
#define TIME_START  69
#define NB          8
#define NT_SEQ      2048
#define ND          1024
#define N_ACT       64
#define N_TIME      32
#define N_COLS      96
#define M_TOT       (NB * NT_SEQ)
#define ACT_ELEMS   ((size_t)M_TOT * N_ACT)

// GEMM tiling
#define BM       64
#define BK       64
#define NTILES   (ND / BK)     // 16
#define ASTR     72            // smem row stride in halves
#define BSTR     72
#define GEMM_BLOCKS (M_TOT / BM)   // 256
#define SIM_PER_B   32

// ---------------- scratch ----------------
__device__ __align__(16) __half g_Bh[N_COLS * ND];   // folded weights, fp16
__device__ int   g_qlist[NB][NT_SEQ];
__device__ int   g_klist[NB][NT_SEQ];
__device__ int   g_kcls [NB][NT_SEQ];
__device__ int   g_qcnt[NB];
__device__ int   g_kcnt[NB];
__device__ float g_krn[NB][NT_SEQ];                  // 1/||h_k|| for listed keys
__device__ float g_cbuf[NB][NT_SEQ][N_COLS];         // per-query copy-logit sums

// ---------------- helpers ----------------
__device__ __forceinline__ float softplus_f(float x) {
    return (x > 20.0f) ? x : log1pf(expf(x));
}
__device__ __forceinline__ uint32_t smem_u32(const void* p) {
    uint32_t a;
    asm("{ .reg .u64 t; cvta.to.shared.u64 t, %1; cvt.u32.u64 %0, t; }" : "=r"(a) : "l"(p));
    return a;
}
__device__ __forceinline__ void ldsm4(uint32_t* r, uint32_t addr) {
    asm volatile("ldmatrix.sync.aligned.m8n8.x4.shared.b16 {%0,%1,%2,%3}, [%4];"
                 : "=r"(r[0]), "=r"(r[1]), "=r"(r[2]), "=r"(r[3]) : "r"(addr));
}
__device__ __forceinline__ void mma_f16(float* c, const uint32_t* a, const uint32_t* b) {
    asm volatile(
        "mma.sync.aligned.m16n8k16.row.col.f32.f16.f16.f32 "
        "{%0,%1,%2,%3}, {%4,%5,%6,%7}, {%8,%9}, {%0,%1,%2,%3};"
        : "+f"(c[0]), "+f"(c[1]), "+f"(c[2]), "+f"(c[3])
        : "r"(a[0]), "r"(a[1]), "r"(a[2]), "r"(a[3]), "r"(b[0]), "r"(b[1]));
}
__device__ __forceinline__ void cvt16(const float4* f, uint4& o0, uint4& o1) {
    uint32_t u[8];
    #pragma unroll
    for (int i = 0; i < 4; i++) {
        __half2 a = __float22half2_rn(make_float2(f[i].x, f[i].y));
        __half2 b = __float22half2_rn(make_float2(f[i].z, f[i].w));
        u[2 * i]     = *(uint32_t*)&a;
        u[2 * i + 1] = *(uint32_t*)&b;
    }
    o0 = make_uint4(u[0], u[1], u[2], u[3]);
    o1 = make_uint4(u[4], u[5], u[6], u[7]);
}

// ---------------- kernel 1: weight-fold (float4) + token scan + key norms ----------------
#define WC_BLOCKS 96   // 96*1024 elems / (256 thr * 4 per thr)

__global__ void prep_kernel(const float* __restrict__ E,
                            const float* __restrict__ Wn,
                            const float* __restrict__ Wt,
                            const float* __restrict__ tsa, const float* __restrict__ tst,
                            const int* __restrict__ tokens,
                            const float* __restrict__ h) {
    if (blockIdx.x < WC_BLOCKS) {
        int i4 = (blockIdx.x * blockDim.x + threadIdx.x) * 4;
        float sa = softplus_f(*tsa);
        float st = softplus_f(*tst);
        int r = i4 >> 10;
        int c = i4 & (ND - 1);
        float4 w, e;
        float s;
        if (r < N_ACT) {
            w = *(const float4*)(Wn + r * ND + c);
            e = *(const float4*)(E + (ACT_START + r) * ND + c);
            s = sa;
        } else {
            w = *(const float4*)(Wt + (r - N_ACT) * ND + c);
            e = *(const float4*)(E + (TIME_START + (r - N_ACT)) * ND + c);
            s = st;
        }
        __half2 p0 = __float22half2_rn(make_float2(w.x + s * e.x, w.y + s * e.y));
        __half2 p1 = __float22half2_rn(make_float2(w.z + s * e.z, w.w + s * e.w));
        uint2 o = make_uint2(*(uint32_t*)&p0, *(uint32_t*)&p1);
        *(uint2*)(g_Bh + i4) = o;
        return;
    }
    // scan + key norms: one block per batch
    const int b    = blockIdx.x - WC_BLOCKS;
    const int tid  = threadIdx.x;
    const int warp = tid >> 5;
    const int lane = tid & 31;
    const int* tk  = tokens + b * NT_SEQ;

    if (tid == 0) { g_qcnt[b] = 0; g_kcnt[b] = 0; }
    __syncthreads();

    #pragma unroll
    for (int r = 0; r < NT_SEQ / 256; r++) {
        int pos = tid + r * 256;
        int tok = tk[pos];
        if (tok == TOK_LABEL) {
            int s = atomicAdd(&g_qcnt[b], 1);
            g_qlist[b][s] = pos;
        }
        if (pos >= 1 && tok >= ACT_START && tk[pos - 1] == TOK_LABEL) {
            int s = atomicAdd(&g_kcnt[b], 1);
            g_klist[b][s] = pos;
            g_kcls[b][s]  = (tok < TIME_START) ? (tok - ACT_START)
                                               : (N_ACT + (tok - TIME_START));
        }
    }
    __syncthreads();

    // reciprocal norms for the listed keys (warp per key)
    const int kc = g_kcnt[b];
    const float* hb = h + (size_t)b * NT_SEQ * ND;
    for (int j = warp; j < kc; j += 8) {
        const float* row = hb + (size_t)g_klist[b][j] * ND;
        float s = 0.0f;
        #pragma unroll
        for (int c = 0; c < 8; c++) {
            float4 v = *(const float4*)(row + c * 128 + lane * 4);
            s += v.x*v.x + v.y*v.y + v.z*v.z + v.w*v.w;
        }
        #pragma unroll
        for (int o = 16; o; o >>= 1) s += __shfl_xor_sync(0xffffffffu, s, o);
        if (lane == 0) g_krn[b][j] = 1.0f / fmaxf(sqrtf(s), 1e-12f);
    }
}

// ---------------- kernel 2: fp16 GEMM (blocks 0..255) + copy sims (blocks 256..511) ----------------
__global__ __launch_bounds__(256, 2)
void gemm_kernel(const float* __restrict__ h, float* __restrict__ out,
                 const float* __restrict__ bn, const float* __restrict__ bt,
                 const float* __restrict__ cta, const float* __restrict__ ctt) {
    __shared__ __align__(16) __half sA[2][BM * ASTR];       // 2 x 9216 B
    __shared__ __align__(16) __half sB[2][N_COLS * BSTR];   // 2 x 13824 B
    __shared__ float s_bias[N_COLS];   // gemm path; reused as s_acc by sim path

    const int tid  = threadIdx.x;
    const int warp = tid >> 5;
    const int lane = tid & 31;

    // ================= sim path =================
    if (blockIdx.x >= GEMM_BLOCKS) {
        const int sid   = blockIdx.x - GEMM_BLOCKS;
        const int b     = sid >> 5;
        const int qslot = sid & (SIM_PER_B - 1);
        const int qcnt  = g_qcnt[b];
        if (qslot >= qcnt) return;
        const int kc    = g_kcnt[b];
        const float tau_a = softplus_f(*cta);
        const float tau_t = softplus_f(*ctt);
        const float* hb   = h + (size_t)b * NT_SEQ * ND;
        float* s_acc = s_bias;   // reuse shared

        for (int qi = qslot; qi < qcnt; qi += SIM_PER_B) {
            __syncthreads();
            if (tid < N_COLS) s_acc[tid] = 0.0f;
            const int q = g_qlist[b][qi];
            const float* hq = hb + (size_t)q * ND;
            float4 qv[8];
            float nq = 0.0f;
            #pragma unroll
            for (int c = 0; c < 8; c++) {
                qv[c] = *(const float4*)(hq + c * 128 + lane * 4);
                nq += qv[c].x*qv[c].x + qv[c].y*qv[c].y + qv[c].z*qv[c].z + qv[c].w*qv[c].w;
            }
            #pragma unroll
            for (int o = 16; o; o >>= 1) nq += __shfl_xor_sync(0xffffffffu, nq, o);
            const float rnq = 1.0f / fmaxf(sqrtf(nq), 1e-12f);
            __syncthreads();

            for (int j = warp; j < kc; j += 16) {
                const int jb = j + 8;
                const bool h2 = jb < kc;
                int k1 = g_klist[b][j];
                int k2 = h2 ? g_klist[b][jb] : k1;
                bool m1 = (k1 < q);
                bool m2 = h2 && (k2 < q);
                if (!m1 && !m2) continue;
                const float* p1 = hb + (size_t)k1 * ND;
                const float* p2 = hb + (size_t)k2 * ND;
                float d1 = 0.0f, d2 = 0.0f;
                #pragma unroll
                for (int c = 0; c < 8; c++) {
                    float4 a = *(const float4*)(p1 + c * 128 + lane * 4);
                    float4 v = *(const float4*)(p2 + c * 128 + lane * 4);
                    d1 += qv[c].x*a.x + qv[c].y*a.y + qv[c].z*a.z + qv[c].w*a.w;
                    d2 += qv[c].x*v.x + qv[c].y*v.y + qv[c].z*v.z + qv[c].w*v.w;
                }
                #pragma unroll
                for (int o = 16; o; o >>= 1) {
                    d1 += __shfl_xor_sync(0xffffffffu, d1, o);
                    d2 += __shfl_xor_sync(0xffffffffu, d2, o);
                }
                if (lane == 0) {
                    if (m1) {
                        int cls = g_kcls[b][j];
                        float sim = d1 * rnq * g_krn[b][j];
                        atomicAdd(&s_acc[cls], sim * (cls < N_ACT ? tau_a : tau_t));
                    }
                    if (m2) {
                        int cls = g_kcls[b][jb];
                        float sim = d2 * rnq * g_krn[b][jb];
                        atomicAdd(&s_acc[cls], sim * (cls < N_ACT ? tau_a : tau_t));
                    }
                }
            }
            __syncthreads();
            if (tid < N_COLS) g_cbuf[b][qi][tid] = s_acc[tid];
        }
        return;
    }

    // ================= gemm path (unchanged from R7/R8) =================
    const int wm = warp & 1;       // m-tile of 32
    const int wn = warp >> 1;      // n-tile of 24
    const int m0 = blockIdx.x * BM;

    if (tid < N_COLS) s_bias[tid] = (tid < N_ACT) ? bn[tid] : bt[tid - N_ACT];

    const int aRow = tid >> 2;
    const int aK   = (tid & 3) * 16;
    const float* gA = h + (size_t)(m0 + aRow) * ND + aK;

    const int bN = tid >> 1;
    const int bK = (tid & 1) * 32;
    const __half* gB = g_Bh + (size_t)bN * ND + bK;

    float acc[2][3][4];
    #pragma unroll
    for (int i = 0; i < 2; i++)
        #pragma unroll
        for (int j = 0; j < 3; j++)
            #pragma unroll
            for (int c = 0; c < 4; c++) acc[i][j][c] = 0.0f;

    float4 fa[4];
    uint4  pb[4];

    #pragma unroll
    for (int i = 0; i < 4; i++) fa[i] = *(const float4*)(gA + 4 * i);
    if (tid < 192)
        #pragma unroll
        for (int i = 0; i < 4; i++) pb[i] = *(const uint4*)(gB + 8 * i);
    {
        uint4 o0, o1; cvt16(fa, o0, o1);
        __half* dA = &sA[0][aRow * ASTR + aK];
        *(uint4*)dA = o0; *(uint4*)(dA + 8) = o1;
        if (tid < 192) {
            __half* dB = &sB[0][bN * BSTR + bK];
            #pragma unroll
            for (int i = 0; i < 4; i++) *(uint4*)(dB + 8 * i) = pb[i];
        }
    }
    __syncthreads();

    const uint32_t uA0 = smem_u32(&sA[0][0]);
    const uint32_t uA1 = smem_u32(&sA[1][0]);
    const uint32_t aoff0 = (uint32_t)(((wm * 32 +      (lane & 15)) * ASTR + (lane >> 4) * 8) * 2);
    const uint32_t aoff1 = (uint32_t)(((wm * 32 + 16 + (lane & 15)) * ASTR + (lane >> 4) * 8) * 2);

    for (int t = 0; t < NTILES; t++) {
        const int cur = t & 1;
        if (t + 1 < NTILES) {
            const float* a2 = gA + (t + 1) * BK;
            #pragma unroll
            for (int i = 0; i < 4; i++) fa[i] = *(const float4*)(a2 + 4 * i);
            if (tid < 192) {
                const __half* b2 = gB + (t + 1) * BK;
                #pragma unroll
                for (int i = 0; i < 4; i++) pb[i] = *(const uint4*)(b2 + 8 * i);
            }
        }

        const uint32_t uA = cur ? uA1 : uA0;
        const __half* sb = &sB[cur][0];
        #pragma unroll
        for (int ks = 0; ks < 4; ks++) {
            uint32_t a0[4], a1[4];
            ldsm4(a0, uA + aoff0 + ks * 32);
            ldsm4(a1, uA + aoff1 + ks * 32);
            uint32_t b[3][2];
            #pragma unroll
            for (int j = 0; j < 3; j++) {
                int n = wn * 24 + j * 8 + (lane >> 2);
                const __half* p = sb + n * BSTR + ks * 16 + (lane & 3) * 2;
                b[j][0] = *(const uint32_t*)p;
                b[j][1] = *(const uint32_t*)(p + 8);
            }
            #pragma unroll
            for (int j = 0; j < 3; j++) {
                mma_f16(acc[0][j], a0, b[j]);
                mma_f16(acc[1][j], a1, b[j]);
            }
        }

        if (t + 1 < NTILES) {
            const int nxt = cur ^ 1;
            uint4 o0, o1; cvt16(fa, o0, o1);
            __half* dA = &sA[nxt][aRow * ASTR + aK];
            *(uint4*)dA = o0; *(uint4*)(dA + 8) = o1;
            if (tid < 192) {
                __half* dB = &sB[nxt][bN * BSTR + bK];
                #pragma unroll
                for (int i = 0; i < 4; i++) *(uint4*)(dB + 8 * i) = pb[i];
            }
        }
        __syncthreads();
    }

    float* out_time = out + ACT_ELEMS;
    #pragma unroll
    for (int mt = 0; mt < 2; mt++) {
        size_t r0 = (size_t)m0 + wm * 32 + mt * 16 + (lane >> 2);
        size_t r1 = r0 + 8;
        #pragma unroll
        for (int j = 0; j < 3; j++) {
            int c0 = wn * 24 + j * 8 + (lane & 3) * 2;
            float b0 = s_bias[c0], b1 = s_bias[c0 + 1];
            float2 v0 = make_float2(acc[mt][j][0] + b0, acc[mt][j][1] + b1);
            float2 v1 = make_float2(acc[mt][j][2] + b0, acc[mt][j][3] + b1);
            if (c0 < N_ACT) {
                *(float2*)(out + r0 * N_ACT + c0) = v0;
                *(float2*)(out + r1 * N_ACT + c0) = v1;
            } else {
                int ct = c0 - N_ACT;
                *(float2*)(out_time + r0 * N_TIME + ct) = v0;
                *(float2*)(out_time + r1 * N_TIME + ct) = v1;
            }
        }
    }
}

// ---------------- kernel 3: add copy contributions into out ----------------
__global__ __launch_bounds__(96)
void copyadd_kernel(float* __restrict__ out,
                    const float* __restrict__ csa, const float* __restrict__ cst) {
    const int b   = blockIdx.y;
    const int tid = threadIdx.x;
    const int qcnt = g_qcnt[b];
    const float sca = softplus_f(*csa);
    const float sct = softplus_f(*cst);
    float* out_time = out + ACT_ELEMS;

    for (int qi = blockIdx.x; qi < qcnt; qi += gridDim.x) {
        const int q = g_qlist[b][qi];
        const size_t m = (size_t)b * NT_SEQ + q;
        float v = g_cbuf[b][qi][tid];
        if (tid < N_ACT)
            out[m * N_ACT + tid] += sca * v;
        else
            out_time[m * N_TIME + (tid - N_ACT)] += sct * v;
    }
}

// ---------------- launch ----------------
extern "C" void kernel_launch(void* const* d_in, const int* in_sizes, int n_in,
                              void* d_out, int out_size) {
    const int*   tokens = (const int*)  d_in[0];
    const float* h      = (const float*)d_in[1];
    const float* E      = (const float*)d_in[2];
    const float* Wn     = (const float*)d_in[3];
    const float* bn     = (const float*)d_in[4];
    const float* Wt     = (const float*)d_in[5];
    const float* bt     = (const float*)d_in[6];
    const float* tsa    = (const float*)d_in[7];
    const float* tst    = (const float*)d_in[8];
    const float* csa    = (const float*)d_in[9];
    const float* cst    = (const float*)d_in[10];
    const float* cta    = (const float*)d_in[11];
    const float* ctt    = (const float*)d_in[12];
    float* out = (float*)d_out;

    prep_kernel<<<WC_BLOCKS + NB, 256>>>(E, Wn, Wt, tsa, tst, tokens, h);
    gemm_kernel<<<GEMM_BLOCKS + NB * SIM_PER_B, 256>>>(h, out, bn, bt, cta, ctt);
    copyadd_kernel<<<dim3(SIM_PER_B, NB), 96>>>(out, csa, cst);
}